// round 17
// baseline (speedup 1.0000x reference)
#include <cuda_runtime.h>
#include <math.h>
#include <stdint.h>

// Problem constants
#define H      2560
#define ESZ    2048
#define EPER   512
#define IPER   128
#define NB     64
#define NT     32
#define INSZ   128
#define NIN_ROWS 640
#define NTILE  20
#define NCTA   440

// SMEM layout (bytes)
//  [1024..33792)   A_hi: u32 tf32, frag layout [mtks(16)][t(32)][slot(4)]  (32 KB)
//  [33792..50176)  A_lo: bf16 pairs, [mtks(16)][t(32)][half(2)] u32       (16 KB)
//  [50176..66560)  B_hi: u32 tf32, [ksng(64)][l(32)][j(2)]                (16 KB)
//  [66560..74752)  B_lo: bf16 pairs, [ksng(64)][l(32)] u32                (8 KB)
#define SM_AH    1024
#define SM_AL    33792
#define SM_BH    50176
#define SM_BL    66560
#define SMEM_BYTES 74752

// Schedule: 440 CTAs, 1 slab (64 k) per slot.
__constant__ int cArea[NTILE] = {0,0,0,0, 1,1,1,1, 2,2,2,2, 3,3,3,3, 0,1,2,3};
__constant__ int cS[NTILE]    = {18,18,18,18, 26,26,26,26, 26,26,26,26, 18,18,18,18, 18,26,26,18};
__constant__ int cBase[NTILE] = {0,18,36,54, 72,98,124,150, 176,202,228,254, 280,298,316,334, 352,370,396,422};
__constant__ int cUses[NTILE] = {20,20,20,20, 30,30,30,30, 30,30,30,30, 20,20,20,20, 10,10,10,10};

// Scratch (device globals)
__device__ float g_P[2 * NCTA * 128 * NB];
__device__ float g_Iin[NT * NIN_ROWS * NB];
__device__ float g_state[H * NB];
__device__ float g_act[2 * H * NB];
__device__ float g_xrelu[NT * INSZ * NB];

// Sync state (cumulative; replay-safe via base reads)
__device__ unsigned g_cnt0 = 0;
__device__ unsigned g_epoch = 0;
__device__ unsigned g_tileP[NTILE] = {};
__device__ unsigned g_actReady[NTILE] = {};
__device__ unsigned g_consumed[NTILE] = {};

__device__ __forceinline__ void spinGE(volatile unsigned* cnt, unsigned base, unsigned need) {
    while ((unsigned)(*cnt - base) < need) {}
}
__device__ __forceinline__ uint32_t totf32(float x) {
    uint32_t r;
    asm("cvt.rna.tf32.f32 %0, %1;" : "=r"(r) : "f"(x));
    return r;
}
__device__ __forceinline__ uint16_t tobf16(float x) {
    uint16_t r;
    asm("cvt.rn.bf16.f32 %0, %1;" : "=h"(r) : "f"(x));
    return r;
}
__device__ __forceinline__ void mmatf32(float d[4], const uint32_t a[4],
                                        uint32_t b0, uint32_t b1) {
    asm volatile(
        "mma.sync.aligned.m16n8k8.row.col.f32.tf32.tf32.f32 "
        "{%0,%1,%2,%3}, {%4,%5,%6,%7}, {%8,%9}, {%0,%1,%2,%3};"
        : "+f"(d[0]), "+f"(d[1]), "+f"(d[2]), "+f"(d[3])
        : "r"(a[0]), "r"(a[1]), "r"(a[2]), "r"(a[3]), "r"(b0), "r"(b1));
}

// device-wide epoch barrier (prologue only)
__device__ __forceinline__ void gbar(unsigned target) {
    __syncthreads();
    if (threadIdx.x == 0) {
        __threadfence();
        if (atomicAdd(&g_cnt0, 1) == NCTA - 1) {
            atomicExch(&g_cnt0, 0);
            __threadfence();
            atomicAdd(&g_epoch, 1);
        }
        while (*(volatile unsigned*)&g_epoch != target) {}
        __threadfence();
    }
    __syncthreads();
}

// ---------------------------------------------------------------------------
__global__ void __launch_bounds__(128, 3) persist(
    const float* __restrict__ x,
    const float* __restrict__ W_in,
    const float* __restrict__ W_rec,
    const float* __restrict__ b_rec,
    const float* __restrict__ state0,
    float* __restrict__ out)
{
    extern __shared__ float sm[];
    const int bid = blockIdx.x;
    const int tid = threadIdx.x;
    const int w = tid >> 5;
    const int l = tid & 31;

    uint32_t* AH = reinterpret_cast<uint32_t*>(reinterpret_cast<char*>(sm) + SM_AH);
    uint32_t* AL = reinterpret_cast<uint32_t*>(reinterpret_cast<char*>(sm) + SM_AL);
    uint16_t* ALh = reinterpret_cast<uint16_t*>(reinterpret_cast<char*>(sm) + SM_AL);
    uint32_t* BH = reinterpret_cast<uint32_t*>(reinterpret_cast<char*>(sm) + SM_BH);
    uint32_t* BL = reinterpret_cast<uint32_t*>(reinterpret_cast<char*>(sm) + SM_BL);
    uint16_t* BLh = reinterpret_cast<uint16_t*>(reinterpret_cast<char*>(sm) + SM_BL);

    int tile = 0;
#pragma unroll
    for (int t = 1; t < NTILE; ++t)
        if (bid >= cBase[t]) tile = t;
    const int slot  = bid - cBase[tile];
    const int S     = cS[tile];
    const int tbase = cBase[tile];
    const int area  = cArea[tile];
    const int h0    = tile * 128;

    const int aE0 = (area > 0 ? area - 1 : 0);
    const int aE1 = (area < 3 ? area + 1 : 3);
    const int k0E = aE0 * EPER;
    const int lenE = (aE1 - aE0 + 1) * EPER;
    const int k0I = ESZ + area * IPER;

    const int off = slot * 64;
    const int kg  = (off < lenE) ? (k0E + off) : (k0I + (off - lenE));
    const int srcT = kg >> 7;
    const unsigned Ssrc = (unsigned)cS[srcT];
    const unsigned myUses = (unsigned)cUses[tile];

    __shared__ unsigned sB[4];
    if (tid == 0) {
        sB[0] = *(volatile unsigned*)&g_epoch;
        sB[1] = *(volatile unsigned*)&g_tileP[tile];
        sB[2] = *(volatile unsigned*)&g_consumed[tile];
        sB[3] = *(volatile unsigned*)&g_actReady[srcT];
    }
    __syncthreads();
    const unsigned epBase = sB[0], tpBase = sB[1], coBase = sB[2], arBase = sB[3];

    // =======================================================================
    // PROLOGUE
    // =======================================================================
    // A) weights -> masked, tf32-split, scattered into mma fragment layout.
    //    idx = (mtile*8+ks)*32 + t2;  hi -> AH[idx*4+sl] (u32 tf32)
    //                                 lo -> ALh[idx*4+sl] (bf16)
    {
        int i = tid;
        int hg = h0 + i;
        float sgn = (kg < ESZ) ? 1.0f : -1.0f;
        const float* wr = W_rec + (size_t)hg * H + kg;
        int mtile = i >> 4, r = i & 15;
#pragma unroll
        for (int q = 0; q < 16; ++q) {
            float4 v = *reinterpret_cast<const float4*>(wr + q * 4);
            float av[4] = {fabsf(v.x) * sgn, fabsf(v.y) * sgn,
                           fabsf(v.z) * sgn, fabsf(v.w) * sgn};
#pragma unroll
            for (int e = 0; e < 4; ++e) {
                int kl = q * 4 + e;
                if (hg == kg + kl) av[e] = 0.0f;
                int ks = kl >> 3, kk = kl & 7;
                int t2 = (r & 7) * 4 + (kk & 3);
                int sl = (r >> 3) + ((kk >> 2) << 1);
                int idx = ((mtile * 8 + ks) * 32 + t2) * 4 + sl;
                uint32_t hi = totf32(av[e]);
                AH[idx] = hi;
                ALh[idx] = tobf16(av[e] - __uint_as_float(hi));
            }
        }
    }

    // B) state + initial activation (f32 buf0)
    for (int e = bid * 128 + tid; e < NB * H; e += NCTA * 128) {
        int b = e / H, h = e % H;
        float s = state0[e];
        g_state[h * NB + b] = s;
        g_act[h * NB + b] = tanhf(fmaxf(s, 0.0f));
    }

    // C) relu(x) transposed to [t][k][b]
    for (int e = bid * 128 + tid; e < NT * NB * INSZ; e += NCTA * 128) {
        int t = e >> 13;
        int r = e & 8191;
        int b = r >> 7, k = r & 127;
        g_xrelu[(t << 13) + k * 64 + b] = fmaxf(x[e], 0.0f);
    }

    gbar(epBase + 1);

    // D) input GEMM (f32; uses B_hi region as weight smem, pre-step-loop only)
    {
        float* smW = reinterpret_cast<float*>(BH);
        for (int p = bid; p < NT * 40; p += NCTA) {
            int t = p / 40, g = p % 40;
            int hp0 = g * 16;
            __syncthreads();
            for (int r2 = tid; r2 < 16 * 128; r2 += 128) {
                int row = r2 >> 7, kk = r2 & 127;
                int hp = hp0 + row;
                int h = (hp < EPER) ? hp : (ESZ + (hp - EPER));
                smW[row * 128 + kk] = fabsf(W_in[h * INSZ + kk]);
            }
            __syncthreads();
            int row = tid >> 3, bo = tid & 7;
            float acc0[4] = {0.f, 0.f, 0.f, 0.f}, acc1[4] = {0.f, 0.f, 0.f, 0.f};
            const float* xr = g_xrelu + (t << 13);
            for (int k = 0; k < 128; ++k) {
                float wv = smW[row * 128 + k];
                float4 xa = *reinterpret_cast<const float4*>(&xr[k * 64 + bo * 8]);
                float4 xb = *reinterpret_cast<const float4*>(&xr[k * 64 + bo * 8 + 4]);
                acc0[0] = fmaf(wv, xa.x, acc0[0]); acc0[1] = fmaf(wv, xa.y, acc0[1]);
                acc0[2] = fmaf(wv, xa.z, acc0[2]); acc0[3] = fmaf(wv, xa.w, acc0[3]);
                acc1[0] = fmaf(wv, xb.x, acc1[0]); acc1[1] = fmaf(wv, xb.y, acc1[1]);
                acc1[2] = fmaf(wv, xb.z, acc1[2]); acc1[3] = fmaf(wv, xb.w, acc1[3]);
            }
            int hp = hp0 + row;
            float* dst = &g_Iin[(t * NIN_ROWS + hp) * NB + bo * 8];
            *reinterpret_cast<float4*>(dst)     = make_float4(acc0[0], acc0[1], acc0[2], acc0[3]);
            *reinterpret_cast<float4*>(dst + 4) = make_float4(acc1[0], acc1[1], acc1[2], acc1[3]);
        }
        __syncthreads();
    }

    gbar(epBase + 2);

    // =======================================================================
    // 32 STEPS
    // =======================================================================
    const int rlo = (slot * 128) / S, rhi = ((slot + 1) * 128) / S;
    const int rr = tid >> 4;
    const int bq = tid & 15;

    for (int t = 0; t < NT; ++t) {
        const float* actSrc = g_act + (t & 1) * (H * NB);
        float* actDst = g_act + ((t + 1) & 1) * (H * NB);
        float* Pbuf = g_P + (t & 1) * (NCTA * 128 * NB);

        // 1) wait for source tile acts
        if (t > 0) {
            if (tid == 0) {
                spinGE(&g_actReady[srcT], arBase, Ssrc * (unsigned)t);
                __threadfence();
            }
            __syncthreads();
        }

        // 2) split pass: LDG acts [64k x 64b], tf32/bf16 split -> B_hi/B_lo frags
        {
            const float* src = actSrc + (size_t)kg * 64;
#pragma unroll
            for (int r = 0; r < 8; ++r) {
                int u = tid + r * 128;
                int k = u >> 4, n4 = (u & 15) * 4;
                float4 v = *reinterpret_cast<const float4*>(src + k * 64 + n4);
                float vv[4] = {v.x, v.y, v.z, v.w};
                int ks = k >> 3, kk = k & 7;
                int j = kk >> 2;
#pragma unroll
                for (int e = 0; e < 4; ++e) {
                    int n = n4 + e;
                    int lidx = ((n & 7) << 2) | (kk & 3);
                    int ksng = ks * 8 + (n >> 3);
                    uint32_t hi = totf32(vv[e]);
                    BH[ksng * 64 + lidx * 2 + j] = hi;
                    BLh[(ksng * 32 + lidx) * 2 + j] =
                        tobf16(vv[e] - __uint_as_float(hi));
                }
            }
            __syncthreads();
        }
        if (tid == 0) { __threadfence(); atomicAdd(&g_consumed[srcT], 1); }

        // 3) MMA: tf32 2-term split, all operands pre-split in smem.
        float acc[2][8][4];
#pragma unroll
        for (int mt = 0; mt < 2; ++mt)
#pragma unroll
            for (int ng = 0; ng < 8; ++ng)
#pragma unroll
                for (int p = 0; p < 4; ++p) acc[mt][ng][p] = 0.f;

#pragma unroll
        for (int ks = 0; ks < 8; ++ks) {
            uint32_t ah[2][4], al[2][4];
#pragma unroll
            for (int mt = 0; mt < 2; ++mt) {
                int idx = ((2 * w + mt) * 8 + ks) * 32 + l;
                uint4 h4 = *reinterpret_cast<const uint4*>(&AH[idx * 4]);
                ah[mt][0] = h4.x; ah[mt][1] = h4.y; ah[mt][2] = h4.z; ah[mt][3] = h4.w;
                uint2 l2 = *reinterpret_cast<const uint2*>(&AL[idx * 2]);
                al[mt][0] = l2.x << 16;
                al[mt][1] = l2.x & 0xFFFF0000u;
                al[mt][2] = l2.y << 16;
                al[mt][3] = l2.y & 0xFFFF0000u;
            }
#pragma unroll
            for (int ng = 0; ng < 8; ++ng) {
                int ksng = ks * 8 + ng;
                uint2 bh = *reinterpret_cast<const uint2*>(&BH[ksng * 64 + l * 2]);
                uint32_t blu = BL[ksng * 32 + l];
                uint32_t bl0 = blu << 16;
                uint32_t bl1 = blu & 0xFFFF0000u;
#pragma unroll
                for (int mt = 0; mt < 2; ++mt) {
                    mmatf32(acc[mt][ng], ah[mt], bh.x, bh.y);
                    mmatf32(acc[mt][ng], ah[mt], bl0, bl1);
                    mmatf32(acc[mt][ng], al[mt], bh.x, bh.y);
                }
            }
        }

        // 4) write partials: D map r=(l/4, l/4+8), c=(l%4)*2 within ng*8
        {
            int r0 = l >> 2, c0 = (l & 3) * 2;
#pragma unroll
            for (int mt = 0; mt < 2; ++mt) {
                int hb = bid * 128 + w * 32 + mt * 16;
                float* p0 = Pbuf + (size_t)(hb + r0) * NB;
                float* p1 = Pbuf + (size_t)(hb + r0 + 8) * NB;
#pragma unroll
                for (int ng = 0; ng < 8; ++ng) {
                    *reinterpret_cast<float2*>(p0 + ng * 8 + c0) =
                        make_float2(acc[mt][ng][0], acc[mt][ng][1]);
                    *reinterpret_cast<float2*>(p1 + ng * 8 + c0) =
                        make_float2(acc[mt][ng][2], acc[mt][ng][3]);
                }
            }
        }

        // 5) tile partial-sync + act-buffer WAR guard
        __syncthreads();
        if (tid == 0) {
            __threadfence();
            atomicAdd(&g_tileP[tile], 1);
            spinGE(&g_tileP[tile], tpBase, (unsigned)S * (unsigned)(t + 1));
            spinGE(&g_consumed[tile], coBase, myUses * (unsigned)t);
            __threadfence();
        }
        __syncthreads();

        // 6) update rows [rlo, rhi)
        for (int r = rlo + rr; r < rhi; r += 8) {
            int h = h0 + r;
            float4 p = make_float4(0.f, 0.f, 0.f, 0.f);
            for (int s = 0; s < S; ++s) {
                float4 v = *reinterpret_cast<const float4*>(
                    &Pbuf[((size_t)(tbase + s) * 128 + r) * NB + bq * 4]);
                p.x += v.x; p.y += v.y; p.z += v.z; p.w += v.w;
            }
            float br = b_rec[h];
            p.x += br; p.y += br; p.z += br; p.w += br;
            if (h < EPER || (h >= ESZ && h < ESZ + IPER)) {
                int hp = (h < EPER) ? h : (EPER + (h - ESZ));
                float4 iv = *reinterpret_cast<const float4*>(
                    &g_Iin[(t * NIN_ROWS + hp) * NB + bq * 4]);
                p.x += iv.x; p.y += iv.y; p.z += iv.z; p.w += iv.w;
            }
            float4 st = *reinterpret_cast<const float4*>(&g_state[h * NB + bq * 4]);
            float4 ns;
            ns.x = st.x * 0.8f + 0.2f * p.x;
            ns.y = st.y * 0.8f + 0.2f * p.y;
            ns.z = st.z * 0.8f + 0.2f * p.z;
            ns.w = st.w * 0.8f + 0.2f * p.w;
            *reinterpret_cast<float4*>(&g_state[h * NB + bq * 4]) = ns;
            float4 a;
            a.x = tanhf(fmaxf(ns.x, 0.0f));
            a.y = tanhf(fmaxf(ns.y, 0.0f));
            a.z = tanhf(fmaxf(ns.z, 0.0f));
            a.w = tanhf(fmaxf(ns.w, 0.0f));
            *reinterpret_cast<float4*>(&actDst[h * NB + bq * 4]) = a;
            out[(t * NB + bq * 4 + 0) * H + h] = a.x;
            out[(t * NB + bq * 4 + 1) * H + h] = a.y;
            out[(t * NB + bq * 4 + 2) * H + h] = a.z;
            out[(t * NB + bq * 4 + 3) * H + h] = a.w;
        }

        // 7) publish acts
        __syncthreads();
        if (tid == 0) { __threadfence(); atomicAdd(&g_actReady[tile], 1); }
    }
}

// ---------------------------------------------------------------------------
extern "C" void kernel_launch(void* const* d_in, const int* in_sizes, int n_in,
                              void* d_out, int out_size) {
    (void)in_sizes; (void)n_in; (void)out_size;
    const float* x      = (const float*)d_in[0];
    const float* W_in   = (const float*)d_in[1];
    const float* W_rec  = (const float*)d_in[2];
    const float* b_rec  = (const float*)d_in[3];
    const float* state0 = (const float*)d_in[4];
    float* out = (float*)d_out;

    cudaFuncSetAttribute(persist,
                         cudaFuncAttributeMaxDynamicSharedMemorySize, SMEM_BYTES);

    persist<<<NCTA, 128, SMEM_BYTES>>>(x, W_in, W_rec, b_rec, state0, out);
}